// round 8
// baseline (speedup 1.0000x reference)
#include <cuda_runtime.h>
#include <cstdint>
#include <math.h>

#define BB   8
#define CLEN 2048
#define QLEN 512
#define DD   1024
#define KTOT (4*DD)

// ---- scratch (static device globals; no allocation allowed) ----
__device__ float g_S[(size_t)BB*CLEN*QLEN];     // similarity / attention  [B,C,Q]
__device__ float g_M[BB*CLEN];                  // rowmax over Q
__device__ float g_Batt[BB*CLEN];               // softmax over C of rowmax
__device__ float g_C2Q[(size_t)BB*CLEN*DD];     // c2q attention output
__device__ float g_Q2Cpart[32*BB*DD];           // partial sums for q2c
__device__ float g_Q2C[BB*DD];                  // q2c attention output
__device__ float g_rowc[BB*CLEN];               // c@w_c + b_c
__device__ float g_rowq[BB*QLEN];               // q@w_q + b_q
__device__ float g_qT[(size_t)BB*DD*QLEN];      // q transposed [B, D, Q]

// ============================ helpers ============================
__device__ __forceinline__ float f2tf32(float x) {
    uint32_t t;
    asm("cvt.rna.tf32.f32 %0, %1;" : "=r"(t) : "f"(x));
    return __uint_as_float(t);
}

__device__ __forceinline__ void mma_tf32(float* d, const uint32_t* a, const uint32_t* b) {
    asm volatile(
        "mma.sync.aligned.m16n8k8.row.col.f32.tf32.tf32.f32 "
        "{%0,%1,%2,%3}, {%4,%5,%6,%7}, {%8,%9}, {%0,%1,%2,%3};"
        : "+f"(d[0]), "+f"(d[1]), "+f"(d[2]), "+f"(d[3])
        : "r"(a[0]), "r"(a[1]), "r"(a[2]), "r"(a[3]), "r"(b[0]), "r"(b[1]));
}

// ============================ global loaders ============================
// A tile: 128 rows (M) x 16 floats (K); thread loads rows ar, ar+64 at k offset ak
template<int MODE>
__device__ __forceinline__ void loadA_g(float4* v, const float* __restrict__ c,
                                        const float* __restrict__ w_cq,
                                        int b, int m0, int ar, int ak, int kt) {
    #pragma unroll
    for (int h = 0; h < 2; h++) {
        int r = ar + h * 64;
        int k = kt * 16 + ak;
        if (MODE == 1) {
            float4 t = *(const float4*)(c + ((size_t)(b * CLEN + m0 + r)) * DD + k);
            float4 w = *(const float4*)(w_cq + k);
            v[h] = make_float4(t.x * w.x, t.y * w.y, t.z * w.z, t.w * w.w);
        } else if (MODE == 2) {
            v[h] = *(const float4*)(g_S + ((size_t)(b * CLEN + m0 + r)) * QLEN + k);
        } else {
            int row = m0 + r;
            int seg = k >> 10;
            int kk  = k & 1023;
            if (seg == 0) {
                v[h] = *(const float4*)(c + (size_t)row * DD + kk);
            } else if (seg == 1) {
                v[h] = *(const float4*)(g_C2Q + (size_t)row * DD + kk);
            } else if (seg == 2) {
                float4 cv = *(const float4*)(c + (size_t)row * DD + kk);
                float4 av = *(const float4*)(g_C2Q + (size_t)row * DD + kk);
                v[h] = make_float4(cv.x * av.x, cv.y * av.y, cv.z * av.z, cv.w * av.w);
            } else {
                float4 cv = *(const float4*)(c + (size_t)row * DD + kk);
                float4 qv = *(const float4*)(g_Q2C + (size_t)b * DD + kk);
                v[h] = make_float4(cv.x * qv.x, cv.y * qv.y, cv.z * qv.z, cv.w * qv.w);
            }
        }
    }
}

// B tile: 256 rows (N) x 16 floats (K); thread loads rows br, br+64, br+128, br+192
template<int MODE>
__device__ __forceinline__ void loadB_g(float4* v, const float* __restrict__ q,
                                        const float* __restrict__ Wl,
                                        int b, int n0, int br, int ak, int kt) {
    #pragma unroll
    for (int h = 0; h < 4; h++) {
        int r = br + h * 64;
        int k = kt * 16 + ak;
        if (MODE == 1) {
            v[h] = *(const float4*)(q + ((size_t)(b * QLEN + n0 + r)) * DD + k);
        } else if (MODE == 2) {
            v[h] = *(const float4*)(g_qT + ((size_t)b * DD + n0 + r) * QLEN + k);
        } else {
            v[h] = *(const float4*)(Wl + (size_t)(n0 + r) * KTOT + k);
        }
    }
}

// ============================ tensor-core GEMM (tf32 mma.sync) ============================
// CTA tile 128x256, 256 threads, 8 warps (2x4), warp tile 64x64, BK=16, double-buffered.
// Fragment-major smem layout (conflict-free consumer LDS.128/LDS.64):
//  A elem (r,k): idx = (((r>>4)*2 + (k>>3))*32 + (r&7)*4 + ((k&3)^(r&3)))*4 + ((k>>2)&1)*2 + ((r>>3)&1)
//  B elem (n,k): idx = (((n>>3)*2 + (k>>3))*32 + (n&7)*4 + ((k&3)^(n&3)))*2 + ((k>>2)&1)
template<int MODE, int KTOTAL>
__global__ __launch_bounds__(256, 1)
void mma_gemm(const float* __restrict__ c, const float* __restrict__ q,
              const float* __restrict__ Wl, const float* __restrict__ w_cq,
              const float* __restrict__ b_cq, const float* __restrict__ b_l,
              float* __restrict__ outp) {
    __shared__ __align__(16) float As[2][2048];
    __shared__ __align__(16) float Bs[2][4096];

    const int tid  = threadIdx.x;
    const int lane = tid & 31;
    const int wid  = tid >> 5;
    const int wm   = wid >> 2;        // 0..1  (64 M-rows each)
    const int wn   = wid & 3;         // 0..3  (64 N-cols each)

    int n0 = blockIdx.x * 256, m0, b;
    if (MODE == 3) { m0 = blockIdx.y * 128; b = m0 / CLEN; }
    else           { b = blockIdx.z; m0 = blockIdx.y * 128; }

    const int ar = tid >> 2;          // 0..63
    const int ak = (tid & 3) * 4;     // 0,4,8,12
    const int ck_p    = ak >> 3;
    const int chalf_p = (ak >> 2) & 1;

    // producer bases: A rows {ar, ar+64}; B rows {ar, ar+64, ar+128, ar+192}
    int aBase[2], xselA[2];
    int bBase[4], xselB[4];
    #pragma unroll
    for (int h = 0; h < 2; h++) {
        int r = ar + h * 64;
        aBase[h] = (((r >> 4) * 2 + ck_p) * 32 + (r & 7) * 4) * 4 + chalf_p * 2 + ((r >> 3) & 1);
        xselA[h] = r & 3;
    }
    #pragma unroll
    for (int h = 0; h < 4; h++) {
        int r = ar + h * 64;
        bBase[h] = (((r >> 3) * 2 + ck_p) * 32 + (r & 7) * 4) * 2 + chalf_p;
        xselB[h] = r & 3;
    }
    const int alane = (lane >> 2) * 4 + ((lane & 3) ^ ((lane >> 2) & 3));

    float acc[4][8][4];
    #pragma unroll
    for (int i = 0; i < 4; i++)
        #pragma unroll
        for (int j = 0; j < 8; j++)
            #pragma unroll
            for (int l = 0; l < 4; l++) acc[i][j][l] = 0.f;

    const int NT = KTOTAL / 16;
    float4 pa[2], pb[4];
    loadA_g<MODE>(pa, c, w_cq, b, m0, ar, ak, 0);
    loadB_g<MODE>(pb, q, Wl, b, n0, ar, ak, 0);

    int p = 0;
    for (int kt = 0; kt < NT; kt++) {
        // commit prefetched tile to smem (fragment-major, tf32 RNA rounded)
        #pragma unroll
        for (int h = 0; h < 2; h++) {
            float av[4] = {pa[h].x, pa[h].y, pa[h].z, pa[h].w};
            #pragma unroll
            for (int j = 0; j < 4; j++)
                As[p][aBase[h] + (j ^ xselA[h]) * 4] = f2tf32(av[j]);
        }
        #pragma unroll
        for (int h = 0; h < 4; h++) {
            float bv[4] = {pb[h].x, pb[h].y, pb[h].z, pb[h].w};
            #pragma unroll
            for (int j = 0; j < 4; j++)
                Bs[p][bBase[h] + (j ^ xselB[h]) * 2] = f2tf32(bv[j]);
        }
        __syncthreads();

        if (kt + 1 < NT) {
            loadA_g<MODE>(pa, c, w_cq, b, m0, ar, ak, kt + 1);
            loadB_g<MODE>(pb, q, Wl, b, n0, ar, ak, kt + 1);
        }

        // compute: 2 k8-blocks, fragments via LDS.128 / LDS.64, 64 MMAs/warp/tile
        #pragma unroll
        for (int ck = 0; ck < 2; ck++) {
            float4 a4[4];
            float2 b2[8];
            #pragma unroll
            for (int mt = 0; mt < 4; mt++)
                a4[mt] = *(const float4*)&As[p][(((wm * 4 + mt) * 2 + ck) * 32 + alane) * 4];
            #pragma unroll
            for (int nt = 0; nt < 8; nt++)
                b2[nt] = *(const float2*)&Bs[p][(((wn * 8 + nt) * 2 + ck) * 32 + alane) * 2];
            #pragma unroll
            for (int mt = 0; mt < 4; mt++)
                #pragma unroll
                for (int nt = 0; nt < 8; nt++)
                    mma_tf32(acc[mt][nt], (const uint32_t*)&a4[mt], (const uint32_t*)&b2[nt]);
        }
        p ^= 1;
    }

    // ---- epilogue ----
    #pragma unroll
    for (int mt = 0; mt < 4; mt++) {
        int mloc0 = wm * 64 + mt * 16 + (lane >> 2);
        #pragma unroll
        for (int half = 0; half < 2; half++) {
            int mloc = mloc0 + half * 8;
            #pragma unroll
            for (int nt = 0; nt < 8; nt++) {
                float v0 = acc[mt][nt][half * 2 + 0];
                float v1 = acc[mt][nt][half * 2 + 1];
                int col = n0 + wn * 64 + nt * 8 + (lane & 3) * 2;
                if (MODE == 1) {
                    float rb = b_cq[0] + g_rowc[b * CLEN + m0 + mloc];
                    float2 o = make_float2(v0 + rb + g_rowq[b * QLEN + col],
                                           v1 + rb + g_rowq[b * QLEN + col + 1]);
                    *(float2*)(g_S + ((size_t)(b * CLEN + m0 + mloc)) * QLEN + col) = o;
                } else if (MODE == 2) {
                    *(float2*)(g_C2Q + ((size_t)(b * CLEN + m0 + mloc)) * DD + col) =
                        make_float2(v0, v1);
                } else {
                    float2 o = make_float2(v0 + b_l[col], v1 + b_l[col + 1]);
                    *(float2*)(outp + ((size_t)(m0 + mloc)) * DD + col) = o;
                }
            }
        }
    }
}

// ============================ small kernels ============================
__global__ void row_reduce_kernel(const float* __restrict__ c, const float* __restrict__ q,
                                  const float* __restrict__ w_c, const float* __restrict__ b_c,
                                  const float* __restrict__ w_q, const float* __restrict__ b_q) {
    int row = blockIdx.x;
    const float* src; const float* w; const float* bias; float* dst;
    if (row < BB*CLEN) { src = c + (size_t)row*DD; w = w_c; bias = b_c; dst = g_rowc + row; }
    else { int r = row - BB*CLEN; src = q + (size_t)r*DD; w = w_q; bias = b_q; dst = g_rowq + r; }
    float s = 0.f;
    for (int k = threadIdx.x; k < DD; k += 128) s += src[k]*w[k];
    __shared__ float red[128];
    red[threadIdx.x] = s; __syncthreads();
    for (int off = 64; off > 0; off >>= 1) {
        if (threadIdx.x < off) red[threadIdx.x] += red[threadIdx.x+off];
        __syncthreads();
    }
    if (threadIdx.x == 0) dst[0] = red[0] + bias[0];
}

__global__ void transpose_q_kernel(const float* __restrict__ q) {
    __shared__ float t[32][33];
    int b = blockIdx.z;
    int q0 = blockIdx.x * 32, d0 = blockIdx.y * 32;
    for (int i = threadIdx.y; i < 32; i += 8)
        t[i][threadIdx.x] = q[((size_t)b*QLEN + q0 + i)*DD + d0 + threadIdx.x];
    __syncthreads();
    for (int i = threadIdx.y; i < 32; i += 8)
        g_qT[((size_t)b*DD + d0 + i)*QLEN + q0 + threadIdx.x] = t[threadIdx.x][i];
}

__global__ void softmax_q_kernel() {
    int row = blockIdx.x;
    float* s = g_S + (size_t)row*QLEN;
    int t = threadIdx.x;
    float v[4];
    float m = -1e30f;
    #pragma unroll
    for (int i=0;i<4;i++){ v[i] = s[t + i*128]; m = fmaxf(m, v[i]); }
    __shared__ float red[128];
    red[t] = m; __syncthreads();
    for (int off=64; off>0; off>>=1){ if (t<off) red[t]=fmaxf(red[t],red[t+off]); __syncthreads(); }
    float rowmax = red[0];
    __syncthreads();
    float sum = 0.f;
    #pragma unroll
    for (int i=0;i<4;i++){ v[i] = __expf(v[i]-rowmax); sum += v[i]; }
    red[t]=sum; __syncthreads();
    for (int off=64; off>0; off>>=1){ if (t<off) red[t]+=red[t+off]; __syncthreads(); }
    float inv = 1.f/red[0];
    #pragma unroll
    for (int i=0;i<4;i++) s[t+i*128] = v[i]*inv;
    if (t==0) g_M[row]=rowmax;
}

__global__ void batt_kernel() {
    int b = blockIdx.x;
    int t = threadIdx.x;
    float v[8]; float m = -1e30f;
    #pragma unroll
    for (int i=0;i<8;i++){ v[i]=g_M[b*CLEN + t + i*256]; m=fmaxf(m,v[i]); }
    __shared__ float red[256];
    red[t]=m; __syncthreads();
    for (int off=128; off>0; off>>=1){ if (t<off) red[t]=fmaxf(red[t],red[t+off]); __syncthreads(); }
    float mx = red[0];
    __syncthreads();
    float sum = 0.f;
    #pragma unroll
    for (int i=0;i<8;i++){ v[i]=__expf(v[i]-mx); sum+=v[i]; }
    red[t]=sum; __syncthreads();
    for (int off=128; off>0; off>>=1){ if (t<off) red[t]+=red[t+off]; __syncthreads(); }
    float inv = 1.f/red[0];
    #pragma unroll
    for (int i=0;i<8;i++) g_Batt[b*CLEN + t + i*256] = v[i]*inv;
}

__global__ void q2c_part_kernel(const float* __restrict__ c) {
    int j = blockIdx.x;
    int b = blockIdx.y;
    int t = threadIdx.x;
    float acc[4] = {0.f,0.f,0.f,0.f};
    int cbase = j*64;
    const float* cb = c + ((size_t)b*CLEN + cbase)*DD;
    for (int cc=0; cc<64; cc++){
        float w = g_Batt[b*CLEN + cbase + cc];
        const float* row = cb + (size_t)cc*DD;
        #pragma unroll
        for (int i=0;i<4;i++) acc[i] += w * row[t + i*256];
    }
    #pragma unroll
    for (int i=0;i<4;i++) g_Q2Cpart[((size_t)j*BB + b)*DD + t + i*256] = acc[i];
}

__global__ void q2c_reduce_kernel() {
    int idx = blockIdx.x*256 + threadIdx.x;
    int b = idx / DD, d = idx % DD;
    float s = 0.f;
    for (int j=0;j<32;j++) s += g_Q2Cpart[((size_t)j*BB + b)*DD + d];
    g_Q2C[idx] = s;
}

// ============================ launch ============================
extern "C" void kernel_launch(void* const* d_in, const int* in_sizes, int n_in,
                              void* d_out, int out_size) {
    const float* c    = (const float*)d_in[0];
    const float* q    = (const float*)d_in[1];
    const float* w_cq = (const float*)d_in[2];
    const float* b_cq = (const float*)d_in[3];
    const float* w_c  = (const float*)d_in[4];
    const float* b_c  = (const float*)d_in[5];
    const float* w_q  = (const float*)d_in[6];
    const float* b_q  = (const float*)d_in[7];
    const float* W_l  = (const float*)d_in[8];
    const float* b_l  = (const float*)d_in[9];
    float* out = (float*)d_out;

    row_reduce_kernel<<<BB*CLEN + BB*QLEN, 128>>>(c, q, w_c, b_c, w_q, b_q);
    transpose_q_kernel<<<dim3(QLEN/32, DD/32, BB), dim3(32, 8)>>>(q);

    mma_gemm<1, DD><<<dim3(QLEN/256, CLEN/128, BB), 256>>>(
        c, q, W_l, w_cq, b_cq, b_l, out);

    softmax_q_kernel<<<BB*CLEN, 128>>>();
    batt_kernel<<<BB, 256>>>();
    q2c_part_kernel<<<dim3(32, BB), 256>>>(c);
    q2c_reduce_kernel<<<(BB*DD)/256, 256>>>();

    mma_gemm<2, QLEN><<<dim3(DD/256, CLEN/128, BB), 256>>>(
        c, q, W_l, w_cq, b_cq, b_l, out);

    mma_gemm<3, KTOT><<<dim3(DD/256, (BB*CLEN)/128, 1), 256>>>(
        c, q, W_l, w_cq, b_cq, b_l, out);
}